// round 1
// baseline (speedup 1.0000x reference)
#include <cuda_runtime.h>
#include <math.h>

#define D_MODEL 512
#define SEQ     1024
#define BATCH   8
#define HEADS   8
#define UNITS   64
#define FF      2048
#define TOKENS  (BATCH*SEQ)                 /* 8192 */
#define QKVN    (2*D_MODEL + HEADS*D_MODEL) /* 5120: [q(512) | k(512) | v(4096)] */

// ---------------------------------------------------------------------------
// Scratch (static __device__ arrays; allocation-free per harness rules)
// ---------------------------------------------------------------------------
__device__ float g_wqkv[D_MODEL * QKVN];                      // packed [d][j]
__device__ float g_qkv[(size_t)TOKENS * QKVN];                // [token][j]
__device__ float g_scores[(size_t)BATCH*HEADS*SEQ*SEQ];       // [b][h][s][t]
__device__ float g_concat[(size_t)TOKENS * HEADS * D_MODEL];  // [token][h*512+e]
__device__ float g_tmp[(size_t)TOKENS * D_MODEL];             // mha / ff2 out
__device__ float g_h[(size_t)TOKENS * D_MODEL];               // LN1 output
__device__ float g_ff1[(size_t)TOKENS * FF];

// ---------------------------------------------------------------------------
// Weight packing: qw[h,d,u], kw[h,d,u], vw[h,d,e]  ->  Wqkv[d][j], j in [0,5120)
// ---------------------------------------------------------------------------
__global__ void pack_w(const float* __restrict__ qw,
                       const float* __restrict__ kw,
                       const float* __restrict__ vw) {
    int idx = blockIdx.x * blockDim.x + threadIdx.x;
    if (idx >= D_MODEL * QKVN) return;
    int d = idx / QKVN;
    int j = idx % QKVN;
    float v;
    if (j < 512) {
        int h = j >> 6, u = j & 63;
        v = qw[(h * D_MODEL + d) * UNITS + u];
    } else if (j < 1024) {
        int jj = j - 512;
        int h = jj >> 6, u = jj & 63;
        v = kw[(h * D_MODEL + d) * UNITS + u];
    } else {
        int jj = j - 1024;
        int h = jj >> 9, e = jj & 511;
        v = vw[(h * D_MODEL + d) * D_MODEL + e];
    }
    g_wqkv[idx] = v;
}

// ---------------------------------------------------------------------------
// Generic batched tiled SGEMM: C = A @ B(^T) (+bias)(+relu)
// Tiles: 128x128x16, 256 threads, 8x8 per-thread microtile.
// All M,N multiples of 128 and K multiples of 16 (true for every call here),
// so no bounds checks.
// Batch bi = blockIdx.z decomposed as (bi/inner, bi%inner) with separate
// outer/inner element strides per operand (handles [b][h] addressing).
// ---------------------------------------------------------------------------
struct GemmP {
    const float* A; const float* B; float* C; const float* bias;
    int K, lda, ldb, ldc;
    long aOut, aIn, bOut, bIn, cOut, cIn;
    int inner, transB, relu;
};

__global__ __launch_bounds__(256) void gemm_k(GemmP p) {
    const int bi = blockIdx.z;
    const int bo = bi / p.inner;
    const int bn = bi % p.inner;
    const float* A = p.A + (long)bo * p.aOut + (long)bn * p.aIn;
    const float* B = p.B + (long)bo * p.bOut + (long)bn * p.bIn;
    float*       C = p.C + (long)bo * p.cOut + (long)bn * p.cIn;

    __shared__ float As[16][128];
    __shared__ float Bs[16][128];

    const int tid  = threadIdx.x;
    const int row0 = blockIdx.y * 128;
    const int col0 = blockIdx.x * 128;

    const int aRow = tid >> 2;            // 0..63
    const int aK4  = (tid & 3) << 2;      // 0,4,8,12
    const int bRow = tid >> 5;            // 0..7   (no trans)
    const int bC4  = (tid & 31) << 2;     //        (no trans)
    const int bN   = tid >> 2;            // 0..63  (trans)
    const int bK4  = (tid & 3) << 2;      //        (trans)
    const int ty   = tid >> 4;            // 0..15
    const int tx   = tid & 15;            // 0..15

    float acc[8][8];
#pragma unroll
    for (int i = 0; i < 8; i++)
#pragma unroll
        for (int j = 0; j < 8; j++) acc[i][j] = 0.f;

    for (int k0 = 0; k0 < p.K; k0 += 16) {
        // A tile (transposed into As[k][m]) — float4 along K
#pragma unroll
        for (int rr = 0; rr < 2; rr++) {
            float4 v = *(const float4*)(A + (long)(row0 + aRow + rr * 64) * p.lda + k0 + aK4);
            As[aK4 + 0][aRow + rr * 64] = v.x;
            As[aK4 + 1][aRow + rr * 64] = v.y;
            As[aK4 + 2][aRow + rr * 64] = v.z;
            As[aK4 + 3][aRow + rr * 64] = v.w;
        }
        if (!p.transB) {
#pragma unroll
            for (int rr = 0; rr < 2; rr++) {
                float4 v = *(const float4*)(B + (long)(k0 + bRow + rr * 8) * p.ldb + col0 + bC4);
                *(float4*)&Bs[bRow + rr * 8][bC4] = v;
            }
        } else {
            // B is logically N x K row-major: Bs[k][n] = B[n*ldb + k]
#pragma unroll
            for (int rr = 0; rr < 2; rr++) {
                float4 v = *(const float4*)(B + (long)(col0 + bN + rr * 64) * p.ldb + k0 + bK4);
                Bs[bK4 + 0][bN + rr * 64] = v.x;
                Bs[bK4 + 1][bN + rr * 64] = v.y;
                Bs[bK4 + 2][bN + rr * 64] = v.z;
                Bs[bK4 + 3][bN + rr * 64] = v.w;
            }
        }
        __syncthreads();

#pragma unroll
        for (int kk = 0; kk < 16; kk++) {
            float a[8], b[8];
#pragma unroll
            for (int i = 0; i < 8; i++) a[i] = As[kk][ty * 8 + i];
#pragma unroll
            for (int j = 0; j < 8; j++) b[j] = Bs[kk][tx * 8 + j];
#pragma unroll
            for (int i = 0; i < 8; i++)
#pragma unroll
                for (int j = 0; j < 8; j++) acc[i][j] += a[i] * b[j];
        }
        __syncthreads();
    }

#pragma unroll
    for (int i = 0; i < 8; i++) {
        const int r = row0 + ty * 8 + i;
#pragma unroll
        for (int j = 0; j < 8; j += 4) {
            const int c = col0 + tx * 8 + j;
            float4 v = make_float4(acc[i][j], acc[i][j + 1], acc[i][j + 2], acc[i][j + 3]);
            if (p.bias) {
                v.x += p.bias[c];     v.y += p.bias[c + 1];
                v.z += p.bias[c + 2]; v.w += p.bias[c + 3];
            }
            if (p.relu) {
                v.x = fmaxf(v.x, 0.f); v.y = fmaxf(v.y, 0.f);
                v.z = fmaxf(v.z, 0.f); v.w = fmaxf(v.w, 0.f);
            }
            *(float4*)(C + (long)r * p.ldc + c) = v;
        }
    }
}

// ---------------------------------------------------------------------------
// Softmax over rows of 1024 (in place), scale applied before max-subtraction.
// One block (256 threads) per row; single pass through the row in registers.
// ---------------------------------------------------------------------------
__device__ __forceinline__ float warp_max(float v) {
#pragma unroll
    for (int o = 16; o; o >>= 1) v = fmaxf(v, __shfl_xor_sync(0xffffffffu, v, o));
    return v;
}
__device__ __forceinline__ float warp_sum(float v) {
#pragma unroll
    for (int o = 16; o; o >>= 1) v += __shfl_xor_sync(0xffffffffu, v, o);
    return v;
}

__global__ __launch_bounds__(256) void softmax_k(float* __restrict__ s) {
    const float scale = 0.04419417382415922f; // 1/sqrt(512)
    float* row = s + (size_t)blockIdx.x * SEQ;
    const int t = threadIdx.x;
    __shared__ float red[8];

    float v[4];
    float mx = -1e30f;
#pragma unroll
    for (int i = 0; i < 4; i++) {
        v[i] = row[t + i * 256] * scale;
        mx = fmaxf(mx, v[i]);
    }
    mx = warp_max(mx);
    if ((t & 31) == 0) red[t >> 5] = mx;
    __syncthreads();
    mx = fmaxf(fmaxf(fmaxf(red[0], red[1]), fmaxf(red[2], red[3])),
               fmaxf(fmaxf(red[4], red[5]), fmaxf(red[6], red[7])));
    __syncthreads();

    float sum = 0.f;
#pragma unroll
    for (int i = 0; i < 4; i++) {
        v[i] = __expf(v[i] - mx);
        sum += v[i];
    }
    sum = warp_sum(sum);
    if ((t & 31) == 0) red[t >> 5] = sum;
    __syncthreads();
    sum = red[0] + red[1] + red[2] + red[3] + red[4] + red[5] + red[6] + red[7];
    const float inv = 1.0f / sum;
#pragma unroll
    for (int i = 0; i < 4; i++) row[t + i * 256] = v[i] * inv;
}

// ---------------------------------------------------------------------------
// out = LayerNorm(a + b) over last dim 512 (eps 1e-3), one block per row.
// Two-pass (mean, then variance) for numerical safety.
// ---------------------------------------------------------------------------
__global__ __launch_bounds__(256) void add_ln_k(const float* __restrict__ a,
                                                const float* __restrict__ b,
                                                const float* __restrict__ gamma,
                                                const float* __restrict__ beta,
                                                float* __restrict__ out) {
    const size_t base = (size_t)blockIdx.x * D_MODEL;
    const int t = threadIdx.x;
    __shared__ float red[8];

    float s0 = a[base + t] + b[base + t];
    float s1 = a[base + t + 256] + b[base + t + 256];

    float sum = warp_sum(s0 + s1);
    if ((t & 31) == 0) red[t >> 5] = sum;
    __syncthreads();
    float mean = (red[0] + red[1] + red[2] + red[3] +
                  red[4] + red[5] + red[6] + red[7]) * (1.0f / D_MODEL);
    __syncthreads();

    const float d0 = s0 - mean, d1 = s1 - mean;
    float sq = warp_sum(d0 * d0 + d1 * d1);
    if ((t & 31) == 0) red[t >> 5] = sq;
    __syncthreads();
    float var = (red[0] + red[1] + red[2] + red[3] +
                 red[4] + red[5] + red[6] + red[7]) * (1.0f / D_MODEL);
    const float inv = rsqrtf(var + 1e-3f);

    out[base + t]       = gamma[t]       * d0 * inv + beta[t];
    out[base + t + 256] = gamma[t + 256] * d1 * inv + beta[t + 256];
}

// ---------------------------------------------------------------------------
// Host side
// ---------------------------------------------------------------------------
static void launch_gemm(const float* A, const float* B, float* C, const float* bias,
                        int M, int N, int K, int lda, int ldb, int ldc,
                        long aOut, long aIn, long bOut, long bIn, long cOut, long cIn,
                        int nb, int inner, int transB, int relu) {
    GemmP p;
    p.A = A; p.B = B; p.C = C; p.bias = bias;
    p.K = K; p.lda = lda; p.ldb = ldb; p.ldc = ldc;
    p.aOut = aOut; p.aIn = aIn; p.bOut = bOut; p.bIn = bIn; p.cOut = cOut; p.cIn = cIn;
    p.inner = inner; p.transB = transB; p.relu = relu;
    dim3 grid(N / 128, M / 128, nb), block(256);
    gemm_k<<<grid, block>>>(p);
}

extern "C" void kernel_launch(void* const* d_in, const int* in_sizes, int n_in,
                              void* d_out, int out_size) {
    const float* x      = (const float*)d_in[0];
    const float* qw     = (const float*)d_in[1];
    const float* kw     = (const float*)d_in[2];
    const float* vw     = (const float*)d_in[3];
    const float* lw     = (const float*)d_in[4];
    const float* gamma1 = (const float*)d_in[5];
    const float* beta1  = (const float*)d_in[6];
    const float* w1     = (const float*)d_in[7];
    const float* b1     = (const float*)d_in[8];
    const float* w2     = (const float*)d_in[9];
    const float* b2     = (const float*)d_in[10];
    const float* gamma2 = (const float*)d_in[11];
    const float* beta2  = (const float*)d_in[12];
    float* out = (float*)d_out;

    float *wqkv, *qkv, *scores, *concat, *tmp, *h, *ff1;
    cudaGetSymbolAddress((void**)&wqkv,   g_wqkv);
    cudaGetSymbolAddress((void**)&qkv,    g_qkv);
    cudaGetSymbolAddress((void**)&scores, g_scores);
    cudaGetSymbolAddress((void**)&concat, g_concat);
    cudaGetSymbolAddress((void**)&tmp,    g_tmp);
    cudaGetSymbolAddress((void**)&h,      g_h);
    cudaGetSymbolAddress((void**)&ff1,    g_ff1);

    // 1. Pack per-head projection weights into one [512, 5120] matrix
    pack_w<<<(D_MODEL * QKVN + 255) / 256, 256>>>(qw, kw, vw);

    // 2. Fused QKV projection: [8192,5120] = x[8192,512] @ Wqkv[512,5120]
    launch_gemm(x, wqkv, qkv, nullptr,
                TOKENS, QKVN, D_MODEL, D_MODEL, QKVN, QKVN,
                0, 0, 0, 0, 0, 0, 1, 1, 0, 0);

    // 3. scores[b,h] = q[b,h] @ k[b,h]^T   (64 batches, bi = b*8 + h)
    launch_gemm(qkv, qkv + 512, scores, nullptr,
                SEQ, SEQ, UNITS, QKVN, QKVN, SEQ,
                (long)SEQ * QKVN, 64,             // A (q): b stride, h stride
                (long)SEQ * QKVN, 64,             // B (k): b stride, h stride
                (long)HEADS * SEQ * SEQ, (long)SEQ * SEQ,  // C (scores)
                BATCH * HEADS, HEADS, 1, 0);

    // 4. Softmax over rows of scores (scale 1/sqrt(512) folded in)
    softmax_k<<<BATCH * HEADS * SEQ, 256>>>(scores);

    // 5. concat[b,s,h*512+e] = probs[b,h] @ v[b,h]
    launch_gemm(scores, qkv + 1024, concat, nullptr,
                SEQ, D_MODEL, SEQ, SEQ, QKVN, HEADS * D_MODEL,
                (long)HEADS * SEQ * SEQ, (long)SEQ * SEQ,   // A (probs)
                (long)SEQ * QKVN, D_MODEL,                  // B (v)
                (long)SEQ * HEADS * D_MODEL, D_MODEL,       // C (concat)
                BATCH * HEADS, HEADS, 0, 0);

    // 6. mha = concat[8192,4096] @ lw[4096,512]
    launch_gemm(concat, lw, tmp, nullptr,
                TOKENS, D_MODEL, HEADS * D_MODEL,
                HEADS * D_MODEL, D_MODEL, D_MODEL,
                0, 0, 0, 0, 0, 0, 1, 1, 0, 0);

    // 7. h = LN1(x + mha)
    add_ln_k<<<TOKENS, 256>>>(x, tmp, gamma1, beta1, h);

    // 8. ff1 = relu(h @ w1 + b1)
    launch_gemm(h, w1, ff1, b1,
                TOKENS, FF, D_MODEL, D_MODEL, FF, FF,
                0, 0, 0, 0, 0, 0, 1, 1, 0, 1);

    // 9. ff2 = ff1 @ w2 + b2
    launch_gemm(ff1, w2, tmp, b2,
                TOKENS, D_MODEL, FF, FF, D_MODEL, D_MODEL,
                0, 0, 0, 0, 0, 0, 1, 1, 0, 0);

    // 10. out = LN2(h + ff2)
    add_ln_k<<<TOKENS, 256>>>(h, tmp, gamma2, beta2, out);
}

// round 6
// speedup vs baseline: 5.9219x; 5.9219x over previous
#include <cuda_runtime.h>
#include <cuda_fp16.h>
#include <cstdint>
#include <math.h>

#define D_MODEL 512
#define SEQ     1024
#define BATCH   8
#define HEADS   8
#define FF      2048
#define TOKENS  (BATCH*SEQ)     /* 8192 */

// ---------------------------------------------------------------------------
// Scratch (static __device__ arrays; allocation-free per harness rules)
// ---------------------------------------------------------------------------
__device__ __half g_xh    [(size_t)TOKENS * D_MODEL];
__device__ __half g_wqkTh [(size_t)1024 * D_MODEL];            // [n=q|k][d]
__device__ __half g_vwTh  [(size_t)HEADS * D_MODEL * D_MODEL]; // [h][e][d]
__device__ __half g_lwTh  [(size_t)D_MODEL * HEADS * D_MODEL]; // [512][4096]
__device__ __half g_w1Th  [(size_t)FF * D_MODEL];              // [2048][512]
__device__ __half g_w2Th  [(size_t)D_MODEL * FF];              // [512][2048]
__device__ __half g_qkh   [(size_t)TOKENS * 1024];             // [token][q|k]
__device__ __half g_vth   [(size_t)BATCH*HEADS * D_MODEL * SEQ];  // [b,h][e][t]
__device__ float  g_scores[(size_t)BATCH*HEADS * SEQ * SEQ];      // fp32
__device__ __half g_probsh[(size_t)BATCH*HEADS * SEQ * SEQ];
__device__ __half g_concath[(size_t)TOKENS * HEADS * D_MODEL];    // [tok][h*512+e]
__device__ float  g_tmp   [(size_t)TOKENS * D_MODEL];
__device__ float  g_h     [(size_t)TOKENS * D_MODEL];
__device__ __half g_hh    [(size_t)TOKENS * D_MODEL];
__device__ __half g_ff1h  [(size_t)TOKENS * FF];

// ---------------------------------------------------------------------------
// PTX helpers (sm_80-era only: cp.async, ldmatrix, mma.sync — all valid on
// plain sm_103 target)
// ---------------------------------------------------------------------------
__device__ __forceinline__ void cp16(uint32_t s, const void* g) {
    asm volatile("cp.async.cg.shared.global [%0], [%1], 16;"
                 :: "r"(s), "l"(__cvta_generic_to_global(g)));
}
#define CP_COMMIT() asm volatile("cp.async.commit_group;" ::: "memory")

__device__ __forceinline__ void ldsm4(uint32_t* r, uint32_t a) {
    asm volatile("ldmatrix.sync.aligned.m8n8.x4.shared.b16 {%0,%1,%2,%3}, [%4];"
                 : "=r"(r[0]), "=r"(r[1]), "=r"(r[2]), "=r"(r[3]) : "r"(a));
}
__device__ __forceinline__ void ldsm2(uint32_t* r, uint32_t a) {
    asm volatile("ldmatrix.sync.aligned.m8n8.x2.shared.b16 {%0,%1}, [%2];"
                 : "=r"(r[0]), "=r"(r[1]) : "r"(a));
}
__device__ __forceinline__ void mma16816(float* d, const uint32_t* a, const uint32_t* b) {
    asm volatile("mma.sync.aligned.m16n8k16.row.col.f32.f16.f16.f32 "
                 "{%0,%1,%2,%3}, {%4,%5,%6,%7}, {%8,%9}, {%0,%1,%2,%3};"
                 : "+f"(d[0]), "+f"(d[1]), "+f"(d[2]), "+f"(d[3])
                 : "r"(a[0]), "r"(a[1]), "r"(a[2]), "r"(a[3]), "r"(b[0]), "r"(b[1]));
}

// ---------------------------------------------------------------------------
// fp16 mma.sync batched GEMM: C[M,N] = A[M,K] @ B[N,K]^T, all operands half,
// K-major rows. Tile 128x128, K-chunk 64 halves (128B rows), 4-stage cp.async,
// 256 threads (8 warps, 2x4 warp grid, 64x32 per warp).
// ---------------------------------------------------------------------------
#define STAGES 4
#define STG    32768                 /* A 16KB + B 16KB per stage */
#define SMEM_TOTAL (STAGES * STG)

struct GemmP {
    const __half* A; const __half* B; float* C; __half* Ch; const float* bias;
    int K, lda, ldb, ldc;
    long aOut, aIn, bOut, bIn, cOut, cIn;
    int inner, relu;
};

__global__ __launch_bounds__(256) void hgemm(GemmP p) {
    extern __shared__ char smem[];
    const uint32_t sb = (uint32_t)__cvta_generic_to_shared(smem);
    const int tid = threadIdx.x, wid = tid >> 5, lane = tid & 31;
    const int wm = wid >> 2, wn = wid & 3;

    const int bi = blockIdx.z, bo = bi / p.inner, bn = bi % p.inner;
    const __half* A = p.A + (long)bo * p.aOut + (long)bn * p.aIn
                          + (long)(blockIdx.y * 128) * p.lda;
    const __half* B = p.B + (long)bo * p.bOut + (long)bn * p.bIn
                          + (long)(blockIdx.x * 128) * p.ldb;

    const int nk = p.K >> 6;

    auto load_stage = [&](int s, int kc) {
        const uint32_t sd = sb + s * STG;
        const __half* ga = A + kc * 64;
        const __half* gb = B + kc * 64;
#pragma unroll
        for (int i = 0; i < 4; i++) {
            int id = tid + i * 256;            // 0..1023
            int row = id >> 3, c = id & 7;
            uint32_t sw = row * 128 + (uint32_t)((c ^ (row & 7)) << 4);
            cp16(sd + sw,         ga + (long)row * p.lda + c * 8);
            cp16(sd + 16384 + sw, gb + (long)row * p.ldb + c * 8);
        }
    };

    // prologue (pad commits so group accounting is uniform)
    for (int s = 0; s < STAGES; s++) {
        if (s < nk) load_stage(s, s);
        CP_COMMIT();
    }

    float acc[4][4][4];
#pragma unroll
    for (int i = 0; i < 4; i++)
#pragma unroll
        for (int j = 0; j < 4; j++)
#pragma unroll
            for (int r = 0; r < 4; r++) acc[i][j][r] = 0.f;

    for (int k = 0; k < nk; k++) {
        const int s = k & (STAGES - 1);
        asm volatile("cp.async.wait_group %0;" :: "n"(STAGES - 1));
        __syncthreads();

        const uint32_t sa = sb + s * STG;
        const uint32_t sB = sa + 16384;
#pragma unroll
        for (int ks = 0; ks < 4; ks++) {
            uint32_t af[4][4], bf[4][2];
#pragma unroll
            for (int mi = 0; mi < 4; mi++) {
                int row = wm * 64 + mi * 16 + (lane & 15);
                int ch = 2 * ks + (lane >> 4);
                ldsm4(af[mi], sa + row * 128 + ((ch ^ (row & 7)) << 4));
            }
#pragma unroll
            for (int ni = 0; ni < 4; ni++) {
                int row = wn * 32 + ni * 8 + (lane & 7);
                int ch = 2 * ks + ((lane >> 3) & 1);
                ldsm2(bf[ni], sB + row * 128 + ((ch ^ (row & 7)) << 4));
            }
#pragma unroll
            for (int mi = 0; mi < 4; mi++)
#pragma unroll
                for (int ni = 0; ni < 4; ni++)
                    mma16816(acc[mi][ni], af[mi], bf[ni]);
        }
        __syncthreads();
        if (k + STAGES < nk) load_stage(s, k + STAGES);
        CP_COMMIT();
    }

    // epilogue
    float* C = p.C ? p.C + (long)bo * p.cOut + (long)bn * p.cIn : nullptr;
    __half* Ch = p.Ch ? p.Ch + (long)bo * p.cOut + (long)bn * p.cIn : nullptr;
    const int g = lane >> 2, tc = (lane & 3) * 2;
#pragma unroll
    for (int mi = 0; mi < 4; mi++) {
        const int r0 = blockIdx.y * 128 + wm * 64 + mi * 16 + g;
#pragma unroll
        for (int ni = 0; ni < 4; ni++) {
            const int c = blockIdx.x * 128 + wn * 32 + ni * 8 + tc;
            float v00 = acc[mi][ni][0], v01 = acc[mi][ni][1];
            float v10 = acc[mi][ni][2], v11 = acc[mi][ni][3];
            if (p.bias) {
                const float b0 = p.bias[c], b1 = p.bias[c + 1];
                v00 += b0; v01 += b1; v10 += b0; v11 += b1;
            }
            if (p.relu) {
                v00 = fmaxf(v00, 0.f); v01 = fmaxf(v01, 0.f);
                v10 = fmaxf(v10, 0.f); v11 = fmaxf(v11, 0.f);
            }
            if (C) {
                *(float2*)(C + (long)r0 * p.ldc + c)       = make_float2(v00, v01);
                *(float2*)(C + (long)(r0 + 8) * p.ldc + c) = make_float2(v10, v11);
            }
            if (Ch) {
                *(__half2*)(Ch + (long)r0 * p.ldc + c)       = __floats2half2_rn(v00, v01);
                *(__half2*)(Ch + (long)(r0 + 8) * p.ldc + c) = __floats2half2_rn(v10, v11);
            }
        }
    }
}

// ---------------------------------------------------------------------------
// Packing / conversion kernels
// ---------------------------------------------------------------------------
__global__ void conv_half(const float* __restrict__ in, __half* __restrict__ out, int n) {
    int i = blockIdx.x * blockDim.x + threadIdx.x;
    if (i < n) out[i] = __float2half_rn(in[i]);
}

__global__ void pack_qk_h(const float* __restrict__ qw, const float* __restrict__ kw) {
    int idx = blockIdx.x * blockDim.x + threadIdx.x;   // 1024*512
    if (idx >= 1024 * 512) return;
    int n = idx >> 9, d = idx & 511;
    float v;
    if (n < 512) { int h = n >> 6, u = n & 63; v = qw[(h * 512 + d) * 64 + u]; }
    else { int nn = n - 512; int h = nn >> 6, u = nn & 63; v = kw[(h * 512 + d) * 64 + u]; }
    g_wqkTh[idx] = __float2half_rn(v);
}

// in[b][R][C] fp32 -> out[b][C][R] half
__global__ void transpose_h(const float* __restrict__ in, __half* __restrict__ out,
                            int R, int C, long inStride, long outStride) {
    __shared__ float t[32][33];
    const long b = blockIdx.z;
    const int r0 = blockIdx.y * 32, c0 = blockIdx.x * 32;
    const float* I = in + b * inStride;
    __half* O = out + b * outStride;
#pragma unroll
    for (int i = 0; i < 32; i += 8)
        t[threadIdx.y + i][threadIdx.x] = I[(long)(r0 + threadIdx.y + i) * C + c0 + threadIdx.x];
    __syncthreads();
#pragma unroll
    for (int i = 0; i < 32; i += 8)
        O[(long)(c0 + threadIdx.y + i) * R + r0 + threadIdx.x] =
            __float2half_rn(t[threadIdx.x][threadIdx.y + i]);
}

// ---------------------------------------------------------------------------
// Softmax (scale folded), fp32 in -> half out
// ---------------------------------------------------------------------------
__device__ __forceinline__ float warp_max(float v) {
#pragma unroll
    for (int o = 16; o; o >>= 1) v = fmaxf(v, __shfl_xor_sync(0xffffffffu, v, o));
    return v;
}
__device__ __forceinline__ float warp_sum(float v) {
#pragma unroll
    for (int o = 16; o; o >>= 1) v += __shfl_xor_sync(0xffffffffu, v, o);
    return v;
}

__global__ __launch_bounds__(256) void softmax_k(const float* __restrict__ s,
                                                 __half* __restrict__ pout) {
    const float scale = 0.04419417382415922f;  // 1/sqrt(512)
    const float* row = s + (size_t)blockIdx.x * SEQ;
    __half* orow = pout + (size_t)blockIdx.x * SEQ;
    const int t = threadIdx.x;
    __shared__ float red[8];
    float v[4];
    float mx = -1e30f;
#pragma unroll
    for (int i = 0; i < 4; i++) { v[i] = row[t + i * 256] * scale; mx = fmaxf(mx, v[i]); }
    mx = warp_max(mx);
    if ((t & 31) == 0) red[t >> 5] = mx;
    __syncthreads();
    mx = fmaxf(fmaxf(fmaxf(red[0], red[1]), fmaxf(red[2], red[3])),
               fmaxf(fmaxf(red[4], red[5]), fmaxf(red[6], red[7])));
    __syncthreads();
    float sum = 0.f;
#pragma unroll
    for (int i = 0; i < 4; i++) { v[i] = __expf(v[i] - mx); sum += v[i]; }
    sum = warp_sum(sum);
    if ((t & 31) == 0) red[t >> 5] = sum;
    __syncthreads();
    sum = red[0] + red[1] + red[2] + red[3] + red[4] + red[5] + red[6] + red[7];
    const float inv = 1.0f / sum;
#pragma unroll
    for (int i = 0; i < 4; i++) orow[t + i * 256] = __float2half_rn(v[i] * inv);
}

// ---------------------------------------------------------------------------
// out = LayerNorm(a + b), optional half copy
// ---------------------------------------------------------------------------
__global__ __launch_bounds__(256) void add_ln_k(const float* __restrict__ a,
                                                const float* __restrict__ b,
                                                const float* __restrict__ gamma,
                                                const float* __restrict__ beta,
                                                float* __restrict__ out,
                                                __half* __restrict__ out_h) {
    const size_t base = (size_t)blockIdx.x * D_MODEL;
    const int t = threadIdx.x;
    __shared__ float red[8];
    float s0 = a[base + t] + b[base + t];
    float s1 = a[base + t + 256] + b[base + t + 256];
    float sum = warp_sum(s0 + s1);
    if ((t & 31) == 0) red[t >> 5] = sum;
    __syncthreads();
    float mean = (red[0]+red[1]+red[2]+red[3]+red[4]+red[5]+red[6]+red[7]) * (1.0f / D_MODEL);
    __syncthreads();
    const float d0 = s0 - mean, d1 = s1 - mean;
    float sq = warp_sum(d0 * d0 + d1 * d1);
    if ((t & 31) == 0) red[t >> 5] = sq;
    __syncthreads();
    float var = (red[0]+red[1]+red[2]+red[3]+red[4]+red[5]+red[6]+red[7]) * (1.0f / D_MODEL);
    const float inv = rsqrtf(var + 1e-3f);
    float o0 = gamma[t]       * d0 * inv + beta[t];
    float o1 = gamma[t + 256] * d1 * inv + beta[t + 256];
    out[base + t] = o0;
    out[base + t + 256] = o1;
    if (out_h) {
        out_h[base + t] = __float2half_rn(o0);
        out_h[base + t + 256] = __float2half_rn(o1);
    }
}

// ---------------------------------------------------------------------------
// Host side
// ---------------------------------------------------------------------------
static void launch_hgemm(const __half* A, const __half* B, float* C, __half* Ch,
                         const float* bias, int M, int N, int K,
                         int lda, int ldb, int ldc,
                         long aOut, long aIn, long bOut, long bIn, long cOut, long cIn,
                         int nb, int inner, int relu) {
    GemmP p;
    p.A = A; p.B = B; p.C = C; p.Ch = Ch; p.bias = bias;
    p.K = K; p.lda = lda; p.ldb = ldb; p.ldc = ldc;
    p.aOut = aOut; p.aIn = aIn; p.bOut = bOut; p.bIn = bIn; p.cOut = cOut; p.cIn = cIn;
    p.inner = inner; p.relu = relu;
    dim3 grid(N / 128, M / 128, nb);
    hgemm<<<grid, 256, SMEM_TOTAL>>>(p);
}

extern "C" void kernel_launch(void* const* d_in, const int* in_sizes, int n_in,
                              void* d_out, int out_size) {
    const float* x      = (const float*)d_in[0];
    const float* qw     = (const float*)d_in[1];
    const float* kw     = (const float*)d_in[2];
    const float* vw     = (const float*)d_in[3];
    const float* lw     = (const float*)d_in[4];
    const float* gamma1 = (const float*)d_in[5];
    const float* beta1  = (const float*)d_in[6];
    const float* w1     = (const float*)d_in[7];
    const float* b1     = (const float*)d_in[8];
    const float* w2     = (const float*)d_in[9];
    const float* b2     = (const float*)d_in[10];
    const float* gamma2 = (const float*)d_in[11];
    const float* beta2  = (const float*)d_in[12];
    float* out = (float*)d_out;

    static int init = 0;
    if (!init) {
        cudaFuncSetAttribute(hgemm, cudaFuncAttributeMaxDynamicSharedMemorySize, SMEM_TOTAL);
        init = 1;
    }

    __half *xh, *wqkTh, *vwTh, *lwTh, *w1Th, *w2Th, *qkh, *vth, *probsh, *concath, *hh, *ff1h;
    float *scores, *tmp, *h;
    cudaGetSymbolAddress((void**)&xh,     g_xh);
    cudaGetSymbolAddress((void**)&wqkTh,  g_wqkTh);
    cudaGetSymbolAddress((void**)&vwTh,   g_vwTh);
    cudaGetSymbolAddress((void**)&lwTh,   g_lwTh);
    cudaGetSymbolAddress((void**)&w1Th,   g_w1Th);
    cudaGetSymbolAddress((void**)&w2Th,   g_w2Th);
    cudaGetSymbolAddress((void**)&qkh,    g_qkh);
    cudaGetSymbolAddress((void**)&vth,    g_vth);
    cudaGetSymbolAddress((void**)&scores, g_scores);
    cudaGetSymbolAddress((void**)&probsh, g_probsh);
    cudaGetSymbolAddress((void**)&concath,g_concath);
    cudaGetSymbolAddress((void**)&tmp,    g_tmp);
    cudaGetSymbolAddress((void**)&h,      g_h);
    cudaGetSymbolAddress((void**)&hh,     g_hh);
    cudaGetSymbolAddress((void**)&ff1h,   g_ff1h);

    // --- pack to fp16 ---
    conv_half<<<(TOKENS * D_MODEL + 255) / 256, 256>>>(x, xh, TOKENS * D_MODEL);
    pack_qk_h<<<(1024 * 512 + 255) / 256, 256>>>(qw, kw);
    { dim3 g(512/32, 512/32, 8);  transpose_h<<<g, dim3(32,8)>>>(vw, vwTh, 512, 512, 512L*512, 512L*512); }
    { dim3 g(512/32, 4096/32, 1); transpose_h<<<g, dim3(32,8)>>>(lw, lwTh, 4096, 512, 0, 0); }
    { dim3 g(2048/32, 512/32, 1); transpose_h<<<g, dim3(32,8)>>>(w1, w1Th, 512, 2048, 0, 0); }
    { dim3 g(512/32, 2048/32, 1); transpose_h<<<g, dim3(32,8)>>>(w2, w2Th, 2048, 512, 0, 0); }

    // 1. qk = x @ [wq|wk]^T : [8192,1024], K=512 (half out only)
    launch_hgemm(xh, wqkTh, nullptr, qkh, nullptr, TOKENS, 1024, 512,
                 512, 512, 1024, 0, 0, 0, 0, 0, 0, 1, 1, 0);

    // 2. vT[b,h][e][t] = vw[h]^T @ x[b]^T : M=512,N=1024,K=512, 64 batches
    launch_hgemm(vwTh, xh, nullptr, vth, nullptr, 512, 1024, 512,
                 512, 512, 1024,
                 0, 512L*512, 1024L*512, 0, 8L*512*1024, 512L*1024,
                 64, 8, 0);

    // 3. scores[b,h] = q @ k^T : M=N=1024, K=64 (fp32 out)
    launch_hgemm(qkh, qkh + 512, scores, nullptr, nullptr, 1024, 1024, 64,
                 1024, 1024, 1024,
                 1024L*1024, 64, 1024L*1024, 64, 8L*1024*1024, 1024L*1024,
                 64, 8, 0);

    // 4. softmax -> half probs
    softmax_k<<<BATCH * HEADS * SEQ, 256>>>(scores, probsh);

    // 5. attn: probs @ v -> concat_h : M=1024,N=512,K=1024, 64 batches
    launch_hgemm(probsh, vth, nullptr, concath, nullptr, 1024, 512, 1024,
                 1024, 1024, 4096,
                 8L*1024*1024, 1024L*1024, 8L*512*1024, 512L*1024,
                 1024L*4096, 512, 64, 8, 0);

    // 6. mha = concat @ lw : [8192,512], K=4096 (fp32 out)
    launch_hgemm(concath, lwTh, tmp, nullptr, nullptr, TOKENS, 512, 4096,
                 4096, 4096, 512, 0, 0, 0, 0, 0, 0, 1, 1, 0);

    // 7. h = LN1(x + mha) (+ half copy)
    add_ln_k<<<TOKENS, 256>>>(x, tmp, gamma1, beta1, h, hh);

    // 8. ff1 = relu(h @ w1 + b1) : [8192,2048], K=512 (half out only)
    launch_hgemm(hh, w1Th, nullptr, ff1h, b1, TOKENS, 2048, 512,
                 512, 512, 2048, 0, 0, 0, 0, 0, 0, 1, 1, 1);

    // 9. ff2 = ff1 @ w2 + b2 : [8192,512], K=2048 (fp32 out)
    launch_hgemm(ff1h, w2Th, tmp, nullptr, b2, TOKENS, 512, 2048,
                 2048, 2048, 512, 0, 0, 0, 0, 0, 0, 1, 1, 0);

    // 10. out = LN2(h + ff2)
    add_ln_k<<<TOKENS, 256>>>(h, tmp, gamma2, beta2, out, nullptr);
}

// round 11
// speedup vs baseline: 7.7319x; 1.3056x over previous
#include <cuda_runtime.h>
#include <cuda_fp16.h>
#include <cstdint>
#include <math.h>

#define D_MODEL 512
#define SEQ     1024
#define BATCH   8
#define HEADS   8
#define FF      2048
#define TOKENS  (BATCH*SEQ)     /* 8192 */

// ---------------------------------------------------------------------------
// Scratch (static __device__ arrays; allocation-free per harness rules)
// ---------------------------------------------------------------------------
__device__ __half g_xh    [(size_t)TOKENS * D_MODEL];
__device__ __half g_wqkTh [(size_t)1024 * D_MODEL];            // [n=q|k][d]
__device__ __half g_vwh   [(size_t)HEADS * D_MODEL * D_MODEL]; // vw as half [h][d'][e]
__device__ __half g_lwTh  [(size_t)D_MODEL * HEADS * D_MODEL]; // [512][4096]
__device__ __half g_WTh   [(size_t)HEADS * D_MODEL * D_MODEL]; // W^T per head [h][d][d']
__device__ __half g_w1Th  [(size_t)FF * D_MODEL];              // [2048][512]
__device__ __half g_w2Th  [(size_t)D_MODEL * FF];              // [512][2048]
__device__ __half g_qkh   [(size_t)TOKENS * 1024];             // [token][q|k]
__device__ __half g_yT    [(size_t)BATCH * D_MODEL * (HEADS*SEQ)]; // [b][d][h*1024+t]
__device__ __half g_scoresh[(size_t)BATCH*HEADS * SEQ * SEQ];      // [b][h][s][t]
__device__ __half g_probs2 [(size_t)BATCH * SEQ * (HEADS*SEQ)];    // [b][s][h*1024+t]
__device__ float  g_tmp   [(size_t)TOKENS * D_MODEL];
__device__ float  g_h     [(size_t)TOKENS * D_MODEL];
__device__ __half g_hh    [(size_t)TOKENS * D_MODEL];
__device__ __half g_ff1h  [(size_t)TOKENS * FF];

// ---------------------------------------------------------------------------
// PTX helpers (sm_80-era: cp.async, ldmatrix, mma.sync — valid on plain sm_103)
// ---------------------------------------------------------------------------
__device__ __forceinline__ void cp16(uint32_t s, const void* g) {
    asm volatile("cp.async.cg.shared.global [%0], [%1], 16;"
                 :: "r"(s), "l"(__cvta_generic_to_global(g)));
}
#define CP_COMMIT() asm volatile("cp.async.commit_group;" ::: "memory")

__device__ __forceinline__ void ldsm4(uint32_t* r, uint32_t a) {
    asm volatile("ldmatrix.sync.aligned.m8n8.x4.shared.b16 {%0,%1,%2,%3}, [%4];"
                 : "=r"(r[0]), "=r"(r[1]), "=r"(r[2]), "=r"(r[3]) : "r"(a));
}
__device__ __forceinline__ void ldsm2(uint32_t* r, uint32_t a) {
    asm volatile("ldmatrix.sync.aligned.m8n8.x2.shared.b16 {%0,%1}, [%2];"
                 : "=r"(r[0]), "=r"(r[1]) : "r"(a));
}
__device__ __forceinline__ void mma16816(float* d, const uint32_t* a, const uint32_t* b) {
    asm volatile("mma.sync.aligned.m16n8k16.row.col.f32.f16.f16.f32 "
                 "{%0,%1,%2,%3}, {%4,%5,%6,%7}, {%8,%9}, {%0,%1,%2,%3};"
                 : "+f"(d[0]), "+f"(d[1]), "+f"(d[2]), "+f"(d[3])
                 : "r"(a[0]), "r"(a[1]), "r"(a[2]), "r"(a[3]), "r"(b[0]), "r"(b[1]));
}

// ---------------------------------------------------------------------------
// fp16 mma.sync batched GEMM: C[M,N] = A[M,K] @ B[N,K]^T, K-major rows.
// Tile 128x128, K-chunk 64 halves, 3-stage cp.async (96KB smem -> 2 CTA/SM),
// 256 threads (8 warps, 2x4 grid, 64x32 per warp).
// ---------------------------------------------------------------------------
#define STAGES 3
#define STG    32768                 /* A 16KB + B 16KB per stage */
#define SMEM_TOTAL (STAGES * STG)

struct GemmP {
    const __half* A; const __half* B; float* C; __half* Ch; const float* bias;
    int K, lda, ldb, ldc;
    long aOut, aIn, bOut, bIn, cOut, cIn;
    int inner, relu;
};

__global__ __launch_bounds__(256) void hgemm(GemmP p) {
    extern __shared__ char smem[];
    const uint32_t sb = (uint32_t)__cvta_generic_to_shared(smem);
    const int tid = threadIdx.x, wid = tid >> 5, lane = tid & 31;
    const int wm = wid >> 2, wn = wid & 3;

    const int bi = blockIdx.z, bo = bi / p.inner, bn = bi % p.inner;
    const __half* A = p.A + (long)bo * p.aOut + (long)bn * p.aIn
                          + (long)(blockIdx.y * 128) * p.lda;
    const __half* B = p.B + (long)bo * p.bOut + (long)bn * p.bIn
                          + (long)(blockIdx.x * 128) * p.ldb;

    const int nk = p.K >> 6;

    auto load_stage = [&](int s, int kc) {
        const uint32_t sd = sb + s * STG;
        const __half* ga = A + kc * 64;
        const __half* gb = B + kc * 64;
#pragma unroll
        for (int i = 0; i < 4; i++) {
            int id = tid + i * 256;            // 0..1023
            int row = id >> 3, c = id & 7;
            uint32_t sw = row * 128 + (uint32_t)((c ^ (row & 7)) << 4);
            cp16(sd + sw,         ga + (long)row * p.lda + c * 8);
            cp16(sd + 16384 + sw, gb + (long)row * p.ldb + c * 8);
        }
    };

    for (int s = 0; s < STAGES; s++) {
        if (s < nk) load_stage(s, s);
        CP_COMMIT();
    }

    float acc[4][4][4];
#pragma unroll
    for (int i = 0; i < 4; i++)
#pragma unroll
        for (int j = 0; j < 4; j++)
#pragma unroll
            for (int r = 0; r < 4; r++) acc[i][j][r] = 0.f;

    int s = 0;
    for (int k = 0; k < nk; k++) {
        asm volatile("cp.async.wait_group %0;" :: "n"(STAGES - 1));
        __syncthreads();

        const uint32_t sa = sb + s * STG;
        const uint32_t sB = sa + 16384;
#pragma unroll
        for (int ks = 0; ks < 4; ks++) {
            uint32_t af[4][4], bf[4][2];
#pragma unroll
            for (int mi = 0; mi < 4; mi++) {
                int row = wm * 64 + mi * 16 + (lane & 15);
                int ch = 2 * ks + (lane >> 4);
                ldsm4(af[mi], sa + row * 128 + ((ch ^ (row & 7)) << 4));
            }
#pragma unroll
            for (int ni = 0; ni < 4; ni++) {
                int row = wn * 32 + ni * 8 + (lane & 7);
                int ch = 2 * ks + ((lane >> 3) & 1);
                ldsm2(bf[ni], sB + row * 128 + ((ch ^ (row & 7)) << 4));
            }
#pragma unroll
            for (int mi = 0; mi < 4; mi++)
#pragma unroll
                for (int ni = 0; ni < 4; ni++)
                    mma16816(acc[mi][ni], af[mi], bf[ni]);
        }
        __syncthreads();
        if (k + STAGES < nk) load_stage(s, k + STAGES);
        CP_COMMIT();
        if (++s == STAGES) s = 0;
    }

    float* C = p.C ? p.C + (long)bo * p.cOut + (long)bn * p.cIn : nullptr;
    __half* Ch = p.Ch ? p.Ch + (long)bo * p.cOut + (long)bn * p.cIn : nullptr;
    const int g = lane >> 2, tc = (lane & 3) * 2;
#pragma unroll
    for (int mi = 0; mi < 4; mi++) {
        const int r0 = blockIdx.y * 128 + wm * 64 + mi * 16 + g;
#pragma unroll
        for (int ni = 0; ni < 4; ni++) {
            const int c = blockIdx.x * 128 + wn * 32 + ni * 8 + tc;
            float v00 = acc[mi][ni][0], v01 = acc[mi][ni][1];
            float v10 = acc[mi][ni][2], v11 = acc[mi][ni][3];
            if (p.bias) {
                const float b0 = p.bias[c], b1 = p.bias[c + 1];
                v00 += b0; v01 += b1; v10 += b0; v11 += b1;
            }
            if (p.relu) {
                v00 = fmaxf(v00, 0.f); v01 = fmaxf(v01, 0.f);
                v10 = fmaxf(v10, 0.f); v11 = fmaxf(v11, 0.f);
            }
            if (C) {
                *(float2*)(C + (long)r0 * p.ldc + c)       = make_float2(v00, v01);
                *(float2*)(C + (long)(r0 + 8) * p.ldc + c) = make_float2(v10, v11);
            }
            if (Ch) {
                *(__half2*)(Ch + (long)r0 * p.ldc + c)       = __floats2half2_rn(v00, v01);
                *(__half2*)(Ch + (long)(r0 + 8) * p.ldc + c) = __floats2half2_rn(v10, v11);
            }
        }
    }
}

// ---------------------------------------------------------------------------
// Packing / conversion kernels
// ---------------------------------------------------------------------------
__global__ void conv_half(const float* __restrict__ in, __half* __restrict__ out, int n) {
    int i = blockIdx.x * blockDim.x + threadIdx.x;
    if (i < n) out[i] = __float2half_rn(in[i]);
}

__global__ void pack_qk_h(const float* __restrict__ qw, const float* __restrict__ kw) {
    int idx = blockIdx.x * blockDim.x + threadIdx.x;   // 1024*512
    if (idx >= 1024 * 512) return;
    int n = idx >> 9, d = idx & 511;
    float v;
    if (n < 512) { int h = n >> 6, u = n & 63; v = qw[(h * 512 + d) * 64 + u]; }
    else { int nn = n - 512; int h = nn >> 6, u = nn & 63; v = kw[(h * 512 + d) * 64 + u]; }
    g_wqkTh[idx] = __float2half_rn(v);
}

// in[b][R][C] fp32 -> out[b][C][R] half
__global__ void transpose_h(const float* __restrict__ in, __half* __restrict__ out,
                            int R, int C, long inStride, long outStride) {
    __shared__ float t[32][33];
    const long b = blockIdx.z;
    const int r0 = blockIdx.y * 32, c0 = blockIdx.x * 32;
    const float* I = in + b * inStride;
    __half* O = out + b * outStride;
#pragma unroll
    for (int i = 0; i < 32; i += 8)
        t[threadIdx.y + i][threadIdx.x] = I[(long)(r0 + threadIdx.y + i) * C + c0 + threadIdx.x];
    __syncthreads();
#pragma unroll
    for (int i = 0; i < 32; i += 8)
        O[(long)(c0 + threadIdx.y + i) * R + r0 + threadIdx.x] =
            __float2half_rn(t[threadIdx.x][threadIdx.y + i]);
}

// ---------------------------------------------------------------------------
// Softmax: half scores [b][h][s][t] -> half probs2 [b][s][h*1024+t]
// ---------------------------------------------------------------------------
__device__ __forceinline__ float warp_max(float v) {
#pragma unroll
    for (int o = 16; o; o >>= 1) v = fmaxf(v, __shfl_xor_sync(0xffffffffu, v, o));
    return v;
}
__device__ __forceinline__ float warp_sum(float v) {
#pragma unroll
    for (int o = 16; o; o >>= 1) v += __shfl_xor_sync(0xffffffffu, v, o);
    return v;
}

__global__ __launch_bounds__(256) void softmax_k(const __half* __restrict__ sc,
                                                 __half* __restrict__ pout) {
    const float scale = 0.04419417382415922f;  // 1/sqrt(512)
    const int i = blockIdx.x;                  // b*8192 + h*1024 + s over [b][h][s]
    const int b = i >> 13, h = (i >> 10) & 7, srow = i & 1023;
    const __half* row = sc + (size_t)i * SEQ;
    __half* orow = pout + ((size_t)(b * 1024 + srow) * 8192) + h * 1024;
    const int t = threadIdx.x;
    __shared__ float red[8];
    float v[4];
    float mx = -1e30f;
#pragma unroll
    for (int j = 0; j < 4; j++) {
        v[j] = __half2float(row[t + j * 256]) * scale;
        mx = fmaxf(mx, v[j]);
    }
    mx = warp_max(mx);
    if ((t & 31) == 0) red[t >> 5] = mx;
    __syncthreads();
    mx = fmaxf(fmaxf(fmaxf(red[0], red[1]), fmaxf(red[2], red[3])),
               fmaxf(fmaxf(red[4], red[5]), fmaxf(red[6], red[7])));
    __syncthreads();
    float sum = 0.f;
#pragma unroll
    for (int j = 0; j < 4; j++) { v[j] = __expf(v[j] - mx); sum += v[j]; }
    sum = warp_sum(sum);
    if ((t & 31) == 0) red[t >> 5] = sum;
    __syncthreads();
    sum = red[0] + red[1] + red[2] + red[3] + red[4] + red[5] + red[6] + red[7];
    const float inv = 1.0f / sum;
#pragma unroll
    for (int j = 0; j < 4; j++) orow[t + j * 256] = __float2half_rn(v[j] * inv);
}

// ---------------------------------------------------------------------------
// out = LayerNorm(a + b), optional half copy
// ---------------------------------------------------------------------------
__global__ __launch_bounds__(256) void add_ln_k(const float* __restrict__ a,
                                                const float* __restrict__ b,
                                                const float* __restrict__ gamma,
                                                const float* __restrict__ beta,
                                                float* __restrict__ out,
                                                __half* __restrict__ out_h) {
    const size_t base = (size_t)blockIdx.x * D_MODEL;
    const int t = threadIdx.x;
    __shared__ float red[8];
    float s0 = a[base + t] + b[base + t];
    float s1 = a[base + t + 256] + b[base + t + 256];
    float sum = warp_sum(s0 + s1);
    if ((t & 31) == 0) red[t >> 5] = sum;
    __syncthreads();
    float mean = (red[0]+red[1]+red[2]+red[3]+red[4]+red[5]+red[6]+red[7]) * (1.0f / D_MODEL);
    __syncthreads();
    const float d0 = s0 - mean, d1 = s1 - mean;
    float sq = warp_sum(d0 * d0 + d1 * d1);
    if ((t & 31) == 0) red[t >> 5] = sq;
    __syncthreads();
    float var = (red[0]+red[1]+red[2]+red[3]+red[4]+red[5]+red[6]+red[7]) * (1.0f / D_MODEL);
    const float inv = rsqrtf(var + 1e-3f);
    float o0 = gamma[t]       * d0 * inv + beta[t];
    float o1 = gamma[t + 256] * d1 * inv + beta[t + 256];
    out[base + t] = o0;
    out[base + t + 256] = o1;
    if (out_h) {
        out_h[base + t] = __float2half_rn(o0);
        out_h[base + t + 256] = __float2half_rn(o1);
    }
}

// ---------------------------------------------------------------------------
// Host side
// ---------------------------------------------------------------------------
static void launch_hgemm(const __half* A, const __half* B, float* C, __half* Ch,
                         const float* bias, int M, int N, int K,
                         int lda, int ldb, int ldc,
                         long aOut, long aIn, long bOut, long bIn, long cOut, long cIn,
                         int nb, int inner, int relu) {
    GemmP p;
    p.A = A; p.B = B; p.C = C; p.Ch = Ch; p.bias = bias;
    p.K = K; p.lda = lda; p.ldb = ldb; p.ldc = ldc;
    p.aOut = aOut; p.aIn = aIn; p.bOut = bOut; p.bIn = bIn; p.cOut = cOut; p.cIn = cIn;
    p.inner = inner; p.relu = relu;
    dim3 grid(N / 128, M / 128, nb);
    hgemm<<<grid, 256, SMEM_TOTAL>>>(p);
}

extern "C" void kernel_launch(void* const* d_in, const int* in_sizes, int n_in,
                              void* d_out, int out_size) {
    const float* x      = (const float*)d_in[0];
    const float* qw     = (const float*)d_in[1];
    const float* kw     = (const float*)d_in[2];
    const float* vw     = (const float*)d_in[3];
    const float* lw     = (const float*)d_in[4];
    const float* gamma1 = (const float*)d_in[5];
    const float* beta1  = (const float*)d_in[6];
    const float* w1     = (const float*)d_in[7];
    const float* b1     = (const float*)d_in[8];
    const float* w2     = (const float*)d_in[9];
    const float* b2     = (const float*)d_in[10];
    const float* gamma2 = (const float*)d_in[11];
    const float* beta2  = (const float*)d_in[12];
    float* out = (float*)d_out;

    static int init = 0;
    if (!init) {
        cudaFuncSetAttribute(hgemm, cudaFuncAttributeMaxDynamicSharedMemorySize, SMEM_TOTAL);
        init = 1;
    }

    __half *xh, *wqkTh, *vwh, *lwTh, *WTh, *w1Th, *w2Th, *qkh, *yT, *scoresh, *probs2, *hh, *ff1h;
    float *tmp, *h;
    cudaGetSymbolAddress((void**)&xh,     g_xh);
    cudaGetSymbolAddress((void**)&wqkTh,  g_wqkTh);
    cudaGetSymbolAddress((void**)&vwh,    g_vwh);
    cudaGetSymbolAddress((void**)&lwTh,   g_lwTh);
    cudaGetSymbolAddress((void**)&WTh,    g_WTh);
    cudaGetSymbolAddress((void**)&w1Th,   g_w1Th);
    cudaGetSymbolAddress((void**)&w2Th,   g_w2Th);
    cudaGetSymbolAddress((void**)&qkh,    g_qkh);
    cudaGetSymbolAddress((void**)&yT,     g_yT);
    cudaGetSymbolAddress((void**)&scoresh,g_scoresh);
    cudaGetSymbolAddress((void**)&probs2, g_probs2);
    cudaGetSymbolAddress((void**)&tmp,    g_tmp);
    cudaGetSymbolAddress((void**)&h,      g_h);
    cudaGetSymbolAddress((void**)&hh,     g_hh);
    cudaGetSymbolAddress((void**)&ff1h,   g_ff1h);

    // --- pack to fp16 ---
    conv_half<<<(TOKENS * D_MODEL + 255) / 256, 256>>>(x, xh, TOKENS * D_MODEL);
    pack_qk_h<<<(1024 * 512 + 255) / 256, 256>>>(qw, kw);
    conv_half<<<(HEADS * 512 * 512 + 255) / 256, 256>>>(vw, vwh, HEADS * 512 * 512);
    { dim3 g(512/32, 4096/32, 1); transpose_h<<<g, dim3(32,8)>>>(lw, lwTh, 4096, 512, 0, 0); }
    { dim3 g(2048/32, 512/32, 1); transpose_h<<<g, dim3(32,8)>>>(w1, w1Th, 512, 2048, 0, 0); }
    { dim3 g(512/32, 2048/32, 1); transpose_h<<<g, dim3(32,8)>>>(w2, w2Th, 2048, 512, 0, 0); }

    // 0. WT_h[d][d'] = sum_e lwT[d][h*512+e] * vwh[h][d'][e]  (8 batches, 512^3)
    launch_hgemm(lwTh, vwh, nullptr, WTh, nullptr, 512, 512, 512,
                 4096, 512, 512,
                 0, 512, 0, 512L*512, 0, 512L*512,
                 8, 8, 0);

    // 1. qk = x @ [wq|wk]^T : [8192,1024], K=512
    launch_hgemm(xh, wqkTh, nullptr, qkh, nullptr, TOKENS, 1024, 512,
                 512, 512, 1024, 0, 0, 0, 0, 0, 0, 1, 1, 0);

    // 2. yT[b][d][h*1024+t] = WT_h @ x[b]^T : M=512(d),N=1024(t),K=512(d'), 64 batches
    launch_hgemm(WTh, xh, nullptr, yT, nullptr, 512, 1024, 512,
                 512, 512, 8192,
                 0, 512L*512, 1024L*512, 0, 512L*8192, 1024,
                 64, 8, 0);

    // 3. scores[b,h] = q @ k^T : M=N=1024, K=64 (half out)
    launch_hgemm(qkh, qkh + 512, nullptr, scoresh, nullptr, 1024, 1024, 64,
                 1024, 1024, 1024,
                 1024L*1024, 64, 1024L*1024, 64, 8L*1024*1024, 1024L*1024,
                 64, 8, 0);

    // 4. softmax -> probs2 [b][s][h*1024+t]
    softmax_k<<<BATCH * HEADS * SEQ, 256>>>(scoresh, probs2);

    // 5. mha[b] = probs2[b] @ yT[b]^T : M=1024,N=512,K=8192, 8 batches (fp32 out)
    launch_hgemm(probs2, yT, tmp, nullptr, nullptr, 1024, 512, 8192,
                 8192, 8192, 512,
                 1024L*8192, 0, 512L*8192, 0, 1024L*512, 0,
                 8, 1, 0);

    // 6. h = LN1(x + mha) (+ half copy)
    add_ln_k<<<TOKENS, 256>>>(x, tmp, gamma1, beta1, h, hh);

    // 7. ff1 = relu(h @ w1 + b1) : [8192,2048], K=512
    launch_hgemm(hh, w1Th, nullptr, ff1h, b1, TOKENS, 2048, 512,
                 512, 512, 2048, 0, 0, 0, 0, 0, 0, 1, 1, 1);

    // 8. ff2 = ff1 @ w2 + b2 : [8192,512], K=2048 (fp32 out)
    launch_hgemm(ff1h, w2Th, tmp, nullptr, b2, TOKENS, 512, 2048,
                 2048, 2048, 512, 0, 0, 0, 0, 0, 0, 1, 1, 0);

    // 9. out = LN2(h + ff2)
    add_ln_k<<<TOKENS, 256>>>(h, tmp, gamma2, beta2, out, nullptr);
}